// round 2
// baseline (speedup 1.0000x reference)
#include <cuda_runtime.h>
#include <math.h>

#define BE 64
#define NOCT 32
#define NSAMP 32768
#define TPB 256
#define NBLK 256            // co-resident: launch_bounds(256,2) -> 296 slots >= 256
#define SPT 32              // be's per thread (one sample each)
#define NWPB 1024           // warps per be (32768 / 32)

// Scratch in device globals (no allocation allowed). g_wmax slots are each
// written exactly once per launch -> no init needed, replay-deterministic.
__device__ float    g_wmax[BE * NWPB];
__device__ float    g_inv[BE];
__device__ int      g_count;
__device__ volatile int g_phase;

// Sense-reversing centralized grid barrier. State is self-restoring across
// graph replays (count returns to 0; phase just keeps flipping).
__device__ __forceinline__ void grid_barrier() {
    __syncthreads();
    if (threadIdx.x == 0) {
        int ph = g_phase;
        __threadfence();
        if (atomicAdd(&g_count, 1) == NBLK - 1) {
            g_count = 0;
            __threadfence();
            g_phase = ph ^ 1;
        } else {
            while (g_phase == ph) { __nanosleep(64); }
        }
        __threadfence();
    }
    __syncthreads();
}

__global__ void __launch_bounds__(TPB, 2)
fused_kernel(const float* __restrict__ f0_in,
             const float* __restrict__ dec_in,
             const float* __restrict__ sp_in,
             float* __restrict__ out) {
    __shared__ float sf[BE * NOCT];
    __shared__ float sa[BE * NOCT];
    __shared__ int   snact[BE];
    __shared__ float sinv[BE];
    __shared__ float wred[TPB / 32];

    const int tid = threadIdx.x;

    // ---- Phase 0: every block computes the full 64-be parameter table ----
    // (phase-critical path uses separate RN ops, sequential f32 cumsum,
    //  matching the reference's f32 rounding exactly)
    if (tid < BE) {
        const float MINF   = (float)(20.0 / 11025.0);
        const float FRANGE = (float)(3000.0 / 11025.0 - 20.0 / 11025.0);
        const float PI_F   = (float)3.14159265358979323846;
        const float RESF   = (float)((1.0 - 0.01) * 0.99);

        float f0  = fabsf(f0_in[tid]);
        float fsc = __fmul_rn(__fadd_rn(MINF, __fmul_rn(f0, FRANGE)), PI_F);
        float sp  = sp_in[tid];

        float x  = dec_in[tid];
        float s1 = 1.0f / (1.0f + expf(-x));
        float s2 = 1.0f / (1.0f + expf(-s1));
        float d  = __fadd_rn(0.01f, __fmul_rn(s2, RESF));
        float ld = logf(__fadd_rn(d, 1e-12f));

        float fac = 0.0f, cl = 0.0f;
        int nact = 0;
        for (int o = 0; o < NOCT; o++) {
            fac = __fadd_rn(fac, sp);
            cl  = __fadd_rn(cl, ld);
            float f0s = __fmul_rn(fsc, fac);
            sf[tid * NOCT + o] = f0s;
            sa[tid * NOCT + o] = expf(cl);
            if (f0s < 1.0f) nact = o + 1;   // monotone -> prefix mask
        }
        snact[tid] = nact;
    }
    __syncthreads();

    // ---- Phase 1: oscillator bank, results held in registers ----
    const int g    = blockIdx.x * TPB + tid;
    const int b0   = g >> 15;                 // 0 or 1 (be parity)
    const int tloc = g & (NSAMP - 1);         // sample index within be
    const float t  = (float)(tloc + 1);

    constexpr double TWO_PI_D = 6.283185307179586476925286766559;
    const float INV2PI = (float)(1.0 / TWO_PI_D);
    const float HI = (float)TWO_PI_D;
    const float LO = (float)(TWO_PI_D - (double)((float)TWO_PI_D));

    float acc[SPT];

    #pragma unroll
    for (int k = 0; k < SPT; k++) {
        const int be = b0 + 2 * k;            // warp-uniform
        const int nact = snact[be];
        const float* fp = sf + be * NOCT;
        const float* ap = sa + be * NOCT;

        float a0 = 0.0f;
        for (int o = 0; o < nact; o++) {
            float f = fp[o];
            float a = ap[o];
            float p = __fmul_rn(f, t);        // match reference fl32 phase
            float kk = rintf(p * INV2PI);
            float r = fmaf(kk, -HI, p);
            r = fmaf(kk, -LO, r);             // exact Cody-Waite 2pi reduction
            a0 = fmaf(__sinf(r), a, a0);
        }
        acc[k] = a0;

        float m = fabsf(a0);
        #pragma unroll
        for (int off = 16; off > 0; off >>= 1)
            m = fmaxf(m, __shfl_xor_sync(0xFFFFFFFFu, m, off));
        if ((tid & 31) == 0)
            g_wmax[be * NWPB + (tloc >> 5)] = m;
    }

    grid_barrier();

    // ---- Phase 2: blocks 0..63 reduce the per-warp maxes of one be ----
    if (blockIdx.x < BE) {
        const int be = blockIdx.x;
        float m = 0.0f;
        #pragma unroll
        for (int j = 0; j < NWPB / TPB; j++)
            m = fmaxf(m, g_wmax[be * NWPB + j * TPB + tid]);
        #pragma unroll
        for (int off = 16; off > 0; off >>= 1)
            m = fmaxf(m, __shfl_xor_sync(0xFFFFFFFFu, m, off));
        if ((tid & 31) == 0) wred[tid >> 5] = m;
        __syncthreads();
        if (tid < TPB / 32) {
            float mm = wred[tid];
            #pragma unroll
            for (int off = TPB / 64; off > 0; off >>= 1)
                mm = fmaxf(mm, __shfl_xor_sync(0xFFu, mm, off));
            if (tid == 0) g_inv[be] = 1.0f / (mm + 1e-8f);
        }
    }

    grid_barrier();

    // ---- Phase 3: normalize from registers, single coalesced store ----
    if (tid < BE) sinv[tid] = g_inv[tid];
    __syncthreads();

    #pragma unroll
    for (int k = 0; k < SPT; k++) {
        const int be = b0 + 2 * k;
        out[be * NSAMP + tloc] = acc[k] * sinv[be];
    }
}

extern "C" void kernel_launch(void* const* d_in, const int* in_sizes, int n_in,
                              void* d_out, int out_size) {
    const float* f0  = (const float*)d_in[0];
    const float* dec = (const float*)d_in[1];
    const float* sp  = (const float*)d_in[2];
    float* out = (float*)d_out;

    fused_kernel<<<NBLK, TPB>>>(f0, dec, sp, out);
}